// round 10
// baseline (speedup 1.0000x reference)
#include <cuda_runtime.h>
#include <math_constants.h>

// Problem constants
#define LQ   15876          // L = 126*126 patches
#define HO   126
#define D    27
#define DP   28             // padded dim; K pad = 1.0 (ssum trick), Q pad = 0
#define SPLIT 9             // split-K over keys (15876 = 9 * 1764)
#define BQ   256            // threads per CTA (1 query per thread)
#define BK   252            // key tile (1764 = 7 * 252); 126 key-pairs
#define NP   (BK / 2)       // 126 pairs per tile
#define NQB  64             // 8x8 CTA tiles of 16x16 queries
#define CH   (LQ / SPLIT)   // 1764 keys per chunk
#define DP2  (DP / 2)       // 14 packed f32x2 values
#define SKIP_THR 22.0f      // log2 skip; measured dropped mass ~1e-9 at 27

// dynamic smem layout (bytes)
#define SKT_OFF 0                       // 126 pairs * 28 u64 = 28224
#define SK_OFF  28224                   // 252 rows * 28 f32  = 28224
#define SNY_OFF 56448                   // 252 f32 (negated yyc) = 1008
#define SMEM_SZ 57472

typedef unsigned long long u64;

// Scratch (no allocations allowed -> device globals)
__device__ __align__(16) float g_K[LQ * DP];          // x patches (keys/vals)
__device__ __align__(16) float g_Q[LQ * DP];          // y patches (queries)
__device__ float g_yyc[LQ];                            // ||X_m||^2 * log2e/0.35
__device__ float g_pm[SPLIT * LQ];                     // partial max (log2 dom)
__device__ __align__(16) float g_pacc[SPLIT * LQ * DP]; // [..27] holds ssum
__device__ __align__(16) float g_outP[LQ * DP];        // attention out patches

__device__ __forceinline__ float ex2(float x) {
    float r;
    asm("ex2.approx.ftz.f32 %0, %1;" : "=f"(r) : "f"(x));
    return r;
}
__device__ __forceinline__ u64 pack2(float a, float b) {
    u64 r;
    asm("mov.b64 %0, {%1, %2};" : "=l"(r) : "f"(a), "f"(b));
    return r;
}
__device__ __forceinline__ void unpack2(u64 v, float& a, float& b) {
    asm("mov.b64 {%0, %1}, %2;" : "=f"(a), "=f"(b) : "l"(v));
}
// d = a*b + c  (packed 2x fp32)
__device__ __forceinline__ u64 fma2v(u64 a, u64 b, u64 c) {
    u64 d;
    asm("fma.rn.f32x2 %0, %1, %2, %3;" : "=l"(d) : "l"(a), "l"(b), "l"(c));
    return d;
}
__device__ __forceinline__ u64 add2v(u64 a, u64 b) {
    u64 d;
    asm("add.rn.f32x2 %0, %1, %2;" : "=l"(d) : "l"(a), "l"(b));
    return d;
}
__device__ __forceinline__ u64 mul2v(u64 a, u64 b) {
    u64 d;
    asm("mul.rn.f32x2 %0, %1, %2;" : "=l"(d) : "l"(a), "l"(b));
    return d;
}
// load two adjacent u64 (16B) from shared
__device__ __forceinline__ void lds_v2u64(u64& a, u64& b, const void* p) {
    asm("ld.shared.v2.b64 {%0, %1}, [%2];"
        : "=l"(a), "=l"(b) : "l"((size_t)__cvta_generic_to_shared(p)));
}
__device__ __forceinline__ u64 lds_u64(const void* p) {
    u64 a;
    asm("ld.shared.b64 %0, [%1];"
        : "=l"(a) : "l"((size_t)__cvta_generic_to_shared(p)));
    return a;
}

// ---------------------------------------------------------------------------
// Kernel A: patch extraction + key squared norms. K pad=1.0, Q pad=0.0
// ---------------------------------------------------------------------------
__global__ void extract_kernel(const float* __restrict__ x,
                               const float* __restrict__ y) {
    int m = blockIdx.x * blockDim.x + threadIdx.x;
    if (m >= LQ) return;
    int ph = m / HO, pw = m % HO;
    const float YSC = 1.4426950408889634f / 0.35f;   // log2e / (h^2 + 0.1)
    float yy = 0.f;
#pragma unroll
    for (int c = 0; c < 3; c++)
#pragma unroll
        for (int ki = 0; ki < 3; ki++)
#pragma unroll
            for (int kj = 0; kj < 3; kj++) {
                int j = c * 9 + ki * 3 + kj;
                float vx = x[c * 16384 + (ph + ki) * 128 + (pw + kj)];
                float vy = y[c * 16384 + (ph + ki) * 128 + (pw + kj)];
                g_K[m * DP + j] = vx;
                g_Q[m * DP + j] = vy;
                yy = fmaf(vx, vx, yy);
            }
    g_K[m * DP + 27] = 1.0f;     // ssum-in-accumulator trick
    g_Q[m * DP + 27] = 0.0f;     // keeps dot product exact
    g_yyc[m] = yy * YSC;
}

// ---------------------------------------------------------------------------
// Kernel B: flash attention, split-K, key-PAIRED packed f32x2 dot.
// sKT holds (k_m[j], k_{m+1}[j]) pairs; qd[j] = (q_j, q_j). One fma2 chain
// yields both dots; one vote/branch per key pair. Slow path (rare) uses the
// row-major sK tile with dim-packed accumulators. acc[27] = softmax mass.
// ---------------------------------------------------------------------------
__global__ __launch_bounds__(BQ, 2) void attn_kernel() {
    extern __shared__ __align__(16) char smem[];
    u64*   sKT = (u64*)(smem + SKT_OFF);     // [NP][DP] key-paired
    float* sK  = (float*)(smem + SK_OFF);    // [BK][DP] row-major
    float* snY = (float*)(smem + SNY_OFF);   // -yyc, paired loads as u64

    int tid = threadIdx.x;
    int w = tid >> 5;                       // warp 0..7
    int lane = tid & 31;
    // CTA tile: 16x16 queries; warp subtile 4x8 (correlated skip sets)
    int bh = blockIdx.x >> 3, bw = blockIdx.x & 7;
    int qrow = min(bh * 16 + (w >> 1) * 4 + (lane >> 3), HO - 1);
    int qcol = min(bw * 16 + (w & 1) * 8 + (lane & 7), HO - 1);
    int ql = qrow * HO + qcol;

    int k0 = blockIdx.y * CH;

    const float S2 = 2.0f * 1.4426950408889634f / 0.35f;
    const u64 S2p = pack2(S2, S2);

    // duplicated query: qd[j] = (q_j, q_j)
    u64 qd[DP];
#pragma unroll
    for (int j = 0; j < DP; j++) {
        float qj = g_Q[ql * DP + j];
        qd[j] = pack2(qj, qj);
    }
    u64 acc[DP2];
#pragma unroll
    for (int j = 0; j < DP2; j++) acc[j] = 0ull;
    float mmax = -CUDART_INF_F;

#pragma unroll 1
    for (int tile = 0; tile < CH / BK; tile++) {
        int kt = k0 + tile * BK;
        // 1) row-major tile (coalesced float4)
        for (int t = tid; t < BK * (DP / 4); t += BQ) {
            ((float4*)sK)[t] = ((const float4*)g_K)[kt * (DP / 4) + t];
        }
        for (int t = tid; t < BK; t += BQ) snY[t] = -g_yyc[kt + t];
        __syncthreads();
        // 2) build key-paired transpose from sK
        for (int t = tid; t < NP * DP; t += BQ) {
            int pp = t / DP, j = t % DP;
            sKT[pp * DP + j] = pack2(sK[(2 * pp) * DP + j],
                                     sK[(2 * pp + 1) * DP + j]);
        }
        __syncthreads();

#pragma unroll 1
        for (int pp = 0; pp < NP; pp++) {
            const char* kp = (const char*)&sKT[pp * DP];
            // paired dot: 2 chains over 28 dims
            u64 e0 = 0ull, e1 = 0ull;
#pragma unroll
            for (int j = 0; j < DP; j += 4) {
                u64 a, b, c, d;
                lds_v2u64(a, b, kp + 8 * j);
                lds_v2u64(c, d, kp + 8 * j + 16);
                e0 = fma2v(qd[j], a, e0);
                e1 = fma2v(qd[j + 1], b, e1);
                e0 = fma2v(qd[j + 2], c, e0);
                e1 = fma2v(qd[j + 3], d, e1);
            }
            u64 e = add2v(e0, e1);                 // (dot_m, dot_m+1)
            u64 ny2 = lds_u64(&snY[2 * pp]);       // (-yy_m, -yy_m+1)
            u64 sc2 = fma2v(e, S2p, ny2);
            float sc_lo, sc_hi;
            unpack2(sc2, sc_lo, sc_hi);
            float scm = fmaxf(sc_lo, sc_hi);

            if (__any_sync(0xffffffffu, scm > mmax - SKIP_THR)) {
                const char* r0 = (const char*)&sK[(2 * pp) * DP];
                // key m
                if (sc_lo > mmax) {
                    float corr = ex2(mmax - sc_lo);
                    u64 c2 = pack2(corr, corr);
#pragma unroll
                    for (int j = 0; j < DP2; j++) acc[j] = mul2v(acc[j], c2);
                    mmax = sc_lo;
                }
                {
                    float p = ex2(sc_lo - mmax);
                    u64 p2 = pack2(p, p);
#pragma unroll
                    for (int j = 0; j < DP2; j += 2) {
                        u64 a, b;
                        lds_v2u64(a, b, r0 + 16 * (j / 2));
                        acc[j]     = fma2v(p2, a, acc[j]);
                        acc[j + 1] = fma2v(p2, b, acc[j + 1]);
                    }
                }
                // key m+1
                if (sc_hi > mmax) {
                    float corr = ex2(mmax - sc_hi);
                    u64 c2 = pack2(corr, corr);
#pragma unroll
                    for (int j = 0; j < DP2; j++) acc[j] = mul2v(acc[j], c2);
                    mmax = sc_hi;
                }
                {
                    float p = ex2(sc_hi - mmax);
                    u64 p2 = pack2(p, p);
                    const char* r1 = r0 + DP * 4;
#pragma unroll
                    for (int j = 0; j < DP2; j += 2) {
                        u64 a, b;
                        lds_v2u64(a, b, r1 + 16 * (j / 2));
                        acc[j]     = fma2v(p2, a, acc[j]);
                        acc[j + 1] = fma2v(p2, b, acc[j + 1]);
                    }
                }
            }
        }
        __syncthreads();
    }

    {
        int sidx = blockIdx.y * LQ + ql;
        g_pm[sidx] = mmax;
        ulonglong2* dst = (ulonglong2*)&g_pacc[(size_t)sidx * DP];
#pragma unroll
        for (int p = 0; p < DP2 / 2; p++) {
            ulonglong2 t;
            t.x = acc[2 * p]; t.y = acc[2 * p + 1];
            dst[p] = t;
        }
    }
}

// ---------------------------------------------------------------------------
// Kernel C: log-sum-exp merge of the SPLIT partials, normalize.
// o[27] = total softmax mass (from the K-pad trick)
// ---------------------------------------------------------------------------
__global__ void merge_kernel() {
    int q = blockIdx.x * blockDim.x + threadIdx.x;
    if (q >= LQ) return;
    float M = -CUDART_INF_F;
#pragma unroll
    for (int s = 0; s < SPLIT; s++) M = fmaxf(M, g_pm[s * LQ + q]);
    float o[DP];
#pragma unroll
    for (int j = 0; j < DP; j++) o[j] = 0.f;
#pragma unroll
    for (int s = 0; s < SPLIT; s++) {
        float w = ex2(g_pm[s * LQ + q] - M);
        const float4* src = (const float4*)&g_pacc[(size_t)(s * LQ + q) * DP];
#pragma unroll
        for (int p = 0; p < DP / 4; p++) {
            float4 t = src[p];
            o[4 * p]     = fmaf(t.x, w, o[4 * p]);
            o[4 * p + 1] = fmaf(t.y, w, o[4 * p + 1]);
            o[4 * p + 2] = fmaf(t.z, w, o[4 * p + 2]);
            o[4 * p + 3] = fmaf(t.w, w, o[4 * p + 3]);
        }
    }
    float inv = 1.0f / o[27];
#pragma unroll
    for (int p = 0; p < DP / 4; p++) {
        float4 t;
        t.x = o[4 * p] * inv; t.y = o[4 * p + 1] * inv;
        t.z = o[4 * p + 2] * inv; t.w = o[4 * p + 3] * inv;
        ((float4*)&g_outP[q * DP])[p] = t;
    }
}

// ---------------------------------------------------------------------------
// Kernel D: overlap-add fold with analytic contribution counts
// ---------------------------------------------------------------------------
__global__ void fold_kernel(float* __restrict__ out) {
    int idx = blockIdx.x * blockDim.x + threadIdx.x;
    if (idx >= 3 * 128 * 128) return;
    int c = idx / 16384;
    int h = (idx / 128) % 128;
    int w = idx % 128;
    int nh = min(h, 125) - max(0, h - 2) + 1;
    int nw = min(w, 125) - max(0, w - 2) + 1;
    float sum = 0.f;
#pragma unroll
    for (int ki = 0; ki < 3; ki++) {
        int ph = h - ki;
        if (ph < 0 || ph >= HO) continue;
#pragma unroll
        for (int kj = 0; kj < 3; kj++) {
            int pw = w - kj;
            if (pw < 0 || pw >= HO) continue;
            sum += g_outP[(ph * HO + pw) * DP + c * 9 + ki * 3 + kj];
        }
    }
    out[idx] = sum / (float)(nh * nw);
}

// ---------------------------------------------------------------------------
extern "C" void kernel_launch(void* const* d_in, const int* in_sizes, int n_in,
                              void* d_out, int out_size) {
    const float* x = (const float*)d_in[0];
    const float* y = (const float*)d_in[1];
    float* out = (float*)d_out;

    cudaFuncSetAttribute(attn_kernel,
                         cudaFuncAttributeMaxDynamicSharedMemorySize, SMEM_SZ);

    extract_kernel<<<(LQ + 255) / 256, 256>>>(x, y);
    dim3 grid(NQB, SPLIT);
    attn_kernel<<<grid, BQ, SMEM_SZ>>>();
    merge_kernel<<<(LQ + 255) / 256, 256>>>();
    fold_kernel<<<(3 * 128 * 128 + 255) / 256, 256>>>(out);
}

// round 11
// speedup vs baseline: 1.1513x; 1.1513x over previous
#include <cuda_runtime.h>
#include <math_constants.h>

// Problem constants
#define LQ   15876          // L = 126*126 patches
#define HO   126
#define D    27
#define DP   28             // padded dim; K pad = 1.0 (ssum trick), Q pad = 0
#define SPLIT 9             // split-K over keys (15876 = 9 * 1764)
#define BQ   256            // threads per CTA (1 query per thread)
#define BK   252            // key tile in smem (1764 = 7 * 252, no tail)
#define NQB  64             // 8x8 CTA tiles of 16x16 queries (covers 126x126)
#define CH   (LQ / SPLIT)   // 1764 keys per chunk
#define DP2  (DP / 2)       // 14 packed f32x2 values
#define SKIP_THR 22.0f      // log2 skip; measured dropped mass ~1e-9 at 27

typedef unsigned long long u64;

// Scratch (no allocations allowed -> device globals)
__device__ __align__(16) float g_K[LQ * DP];          // x patches (keys/vals)
__device__ __align__(16) float g_Q[LQ * DP];          // y patches (queries)
__device__ float g_yyc[LQ];                            // ||X_m||^2 * log2e/0.35
__device__ float g_pm[SPLIT * LQ];                     // partial max (log2 dom)
__device__ __align__(16) float g_pacc[SPLIT * LQ * DP]; // [..27] holds ssum
__device__ __align__(16) float g_outP[LQ * DP];        // attention out patches

__device__ __forceinline__ float ex2(float x) {
    float r;
    asm("ex2.approx.ftz.f32 %0, %1;" : "=f"(r) : "f"(x));
    return r;
}
__device__ __forceinline__ u64 pack2(float a, float b) {
    u64 r;
    asm("mov.b64 %0, {%1, %2};" : "=l"(r) : "f"(a), "f"(b));
    return r;
}
__device__ __forceinline__ void unpack2(u64 v, float& a, float& b) {
    asm("mov.b64 {%0, %1}, %2;" : "=f"(a), "=f"(b) : "l"(v));
}
// d = a*b + c  (packed 2x fp32)
__device__ __forceinline__ u64 fma2v(u64 a, u64 b, u64 c) {
    u64 d;
    asm("fma.rn.f32x2 %0, %1, %2, %3;" : "=l"(d) : "l"(a), "l"(b), "l"(c));
    return d;
}
__device__ __forceinline__ u64 add2v(u64 a, u64 b) {
    u64 d;
    asm("add.rn.f32x2 %0, %1, %2;" : "=l"(d) : "l"(a), "l"(b));
    return d;
}
__device__ __forceinline__ u64 mul2v(u64 a, u64 b) {
    u64 d;
    asm("mul.rn.f32x2 %0, %1, %2;" : "=l"(d) : "l"(a), "l"(b));
    return d;
}
// load two adjacent u64 (16B) from shared
__device__ __forceinline__ void lds_v2u64(u64& a, u64& b, const void* p) {
    asm("ld.shared.v2.b64 {%0, %1}, [%2];"
        : "=l"(a), "=l"(b) : "l"((size_t)__cvta_generic_to_shared(p)));
}

// ---------------------------------------------------------------------------
// Kernel A: patch extraction + key squared norms. K pad=1.0, Q pad=0.0
// ---------------------------------------------------------------------------
__global__ void extract_kernel(const float* __restrict__ x,
                               const float* __restrict__ y) {
    int m = blockIdx.x * blockDim.x + threadIdx.x;
    if (m >= LQ) return;
    int ph = m / HO, pw = m % HO;
    const float YSC = 1.4426950408889634f / 0.35f;   // log2e / (h^2 + 0.1)
    float yy = 0.f;
#pragma unroll
    for (int c = 0; c < 3; c++)
#pragma unroll
        for (int ki = 0; ki < 3; ki++)
#pragma unroll
            for (int kj = 0; kj < 3; kj++) {
                int j = c * 9 + ki * 3 + kj;
                float vx = x[c * 16384 + (ph + ki) * 128 + (pw + kj)];
                float vy = y[c * 16384 + (ph + ki) * 128 + (pw + kj)];
                g_K[m * DP + j] = vx;
                g_Q[m * DP + j] = vy;
                yy = fmaf(vx, vx, yy);
            }
    g_K[m * DP + 27] = 1.0f;     // ssum-in-accumulator trick
    g_Q[m * DP + 27] = 0.0f;     // keeps dot product exact
    g_yyc[m] = yy * YSC;
}

// ---------------------------------------------------------------------------
// Kernel B: flash attention, split-K, packed f32x2 math, threshold skip.
// 2D lane mapping: each warp owns a 4x8 query block (patches overlap ->
// correlated relevant-key sets -> lower warp-union pass rate).
// score (log2 domain): sc = dot * (2*log2e/0.35) - yyc[m]
// acc[27] accumulates the softmax mass (K pad element = 1).
// ---------------------------------------------------------------------------
__global__ __launch_bounds__(BQ, 2) void attn_kernel() {
    __shared__ __align__(16) float sK[BK * DP];
    __shared__ float sY[BK];

    int tid = threadIdx.x;
    int w = tid >> 5;                       // warp 0..7
    int lane = tid & 31;
    // CTA tile: 16x16 queries at (bh*16, bw*16); warp subtile 4x8
    int bh = blockIdx.x >> 3, bw = blockIdx.x & 7;
    int qrow = min(bh * 16 + (w >> 1) * 4 + (lane >> 3), HO - 1);
    int qcol = min(bw * 16 + (w & 1) * 8 + (lane & 7), HO - 1);
    int ql = qrow * HO + qcol;

    int k0 = blockIdx.y * CH;

    const float S2 = 2.0f * 1.4426950408889634f / 0.35f;

    u64 qv[DP2];
#pragma unroll
    for (int p = 0; p < DP2 / 2; p++) {
        ulonglong2 t = ((const ulonglong2*)&g_Q[ql * DP])[p];
        qv[2 * p] = t.x; qv[2 * p + 1] = t.y;
    }
    u64 acc[DP2];
#pragma unroll
    for (int j = 0; j < DP2; j++) acc[j] = 0ull;
    float mmax = -CUDART_INF_F;

#pragma unroll 1
    for (int tile = 0; tile < CH / BK; tile++) {
        int kt = k0 + tile * BK;
        for (int t = tid; t < BK * (DP / 4); t += BQ) {
            ((float4*)sK)[t] = ((const float4*)g_K)[kt * (DP / 4) + t];
        }
        for (int t = tid; t < BK; t += BQ) sY[t] = g_yyc[kt + t];
        __syncthreads();

        for (int kk = 0; kk < BK; kk++) {
            const char* krow = (const char*)&sK[kk * DP];
            u64 kv[DP2];
#pragma unroll
            for (int p = 0; p < DP2 / 2; p++)
                lds_v2u64(kv[2 * p], kv[2 * p + 1], krow + 16 * p);

            // packed dot product, 2 chains
            u64 d0 = fma2v(qv[0], kv[0], 0ull);
            u64 d1 = fma2v(qv[1], kv[1], 0ull);
#pragma unroll
            for (int j = 2; j < DP2; j += 2) {
                d0 = fma2v(qv[j], kv[j], d0);
                d1 = fma2v(qv[j + 1], kv[j + 1], d1);
            }
            d0 = add2v(d0, d1);
            float lo, hi;
            unpack2(d0, lo, hi);
            float sc = fmaf(lo + hi, S2, -sY[kk]);

            // warp-uniform skip: negligible keys never touch ex2 / acc
            if (__any_sync(0xffffffffu, sc > mmax - SKIP_THR)) {
                if (sc > mmax) {            // rare rescale (peaked softmax)
                    float corr = ex2(mmax - sc);
                    u64 c2 = pack2(corr, corr);
#pragma unroll
                    for (int j = 0; j < DP2; j++) acc[j] = mul2v(acc[j], c2);
                    mmax = sc;
                }
                float p = ex2(sc - mmax);
                u64 p2 = pack2(p, p);
#pragma unroll
                for (int j = 0; j < DP2; j++)
                    acc[j] = fma2v(p2, kv[j], acc[j]);
            }
        }
        __syncthreads();
    }

    {
        int sidx = blockIdx.y * LQ + ql;
        g_pm[sidx] = mmax;
        ulonglong2* dst = (ulonglong2*)&g_pacc[(size_t)sidx * DP];
#pragma unroll
        for (int p = 0; p < DP2 / 2; p++) {
            ulonglong2 t;
            t.x = acc[2 * p]; t.y = acc[2 * p + 1];
            dst[p] = t;
        }
    }
}

// ---------------------------------------------------------------------------
// Kernel C: log-sum-exp merge of the SPLIT partials, normalize.
// o[27] = total softmax mass (from the K-pad trick)
// ---------------------------------------------------------------------------
__global__ void merge_kernel() {
    int q = blockIdx.x * blockDim.x + threadIdx.x;
    if (q >= LQ) return;
    float M = -CUDART_INF_F;
#pragma unroll
    for (int s = 0; s < SPLIT; s++) M = fmaxf(M, g_pm[s * LQ + q]);
    float o[DP];
#pragma unroll
    for (int j = 0; j < DP; j++) o[j] = 0.f;
#pragma unroll
    for (int s = 0; s < SPLIT; s++) {
        float w = ex2(g_pm[s * LQ + q] - M);
        const float4* src = (const float4*)&g_pacc[(size_t)(s * LQ + q) * DP];
#pragma unroll
        for (int p = 0; p < DP / 4; p++) {
            float4 t = src[p];
            o[4 * p]     = fmaf(t.x, w, o[4 * p]);
            o[4 * p + 1] = fmaf(t.y, w, o[4 * p + 1]);
            o[4 * p + 2] = fmaf(t.z, w, o[4 * p + 2]);
            o[4 * p + 3] = fmaf(t.w, w, o[4 * p + 3]);
        }
    }
    float inv = 1.0f / o[27];
#pragma unroll
    for (int p = 0; p < DP / 4; p++) {
        float4 t;
        t.x = o[4 * p] * inv; t.y = o[4 * p + 1] * inv;
        t.z = o[4 * p + 2] * inv; t.w = o[4 * p + 3] * inv;
        ((float4*)&g_outP[q * DP])[p] = t;
    }
}

// ---------------------------------------------------------------------------
// Kernel D: overlap-add fold with analytic contribution counts
// ---------------------------------------------------------------------------
__global__ void fold_kernel(float* __restrict__ out) {
    int idx = blockIdx.x * blockDim.x + threadIdx.x;
    if (idx >= 3 * 128 * 128) return;
    int c = idx / 16384;
    int h = (idx / 128) % 128;
    int w = idx % 128;
    int nh = min(h, 125) - max(0, h - 2) + 1;
    int nw = min(w, 125) - max(0, w - 2) + 1;
    float sum = 0.f;
#pragma unroll
    for (int ki = 0; ki < 3; ki++) {
        int ph = h - ki;
        if (ph < 0 || ph >= HO) continue;
#pragma unroll
        for (int kj = 0; kj < 3; kj++) {
            int pw = w - kj;
            if (pw < 0 || pw >= HO) continue;
            sum += g_outP[(ph * HO + pw) * DP + c * 9 + ki * 3 + kj];
        }
    }
    out[idx] = sum / (float)(nh * nw);
}

// ---------------------------------------------------------------------------
extern "C" void kernel_launch(void* const* d_in, const int* in_sizes, int n_in,
                              void* d_out, int out_size) {
    const float* x = (const float*)d_in[0];
    const float* y = (const float*)d_in[1];
    float* out = (float*)d_out;

    extract_kernel<<<(LQ + 255) / 256, 256>>>(x, y);
    dim3 grid(NQB, SPLIT);
    attn_kernel<<<grid, BQ>>>();
    merge_kernel<<<(LQ + 255) / 256, 256>>>();
    fold_kernel<<<(3 * 128 * 128 + 255) / 256, 256>>>(out);
}

// round 12
// speedup vs baseline: 1.1545x; 1.0028x over previous
#include <cuda_runtime.h>
#include <math_constants.h>

// Problem constants
#define LQ   15876          // L = 126*126 patches
#define HO   126
#define D    27
#define DP   28             // padded dim; K pad = 1.0 (ssum trick), Q pad = 0
#define SPLIT 9             // split-K over keys (15876 = 9 * 1764)
#define BQ   256            // threads per CTA (1 query per thread)
#define BK   252            // key tile in smem (1764 = 7 * 252, no tail)
#define NQB  64             // 8x8 CTA tiles of 16x16 queries (covers 126x126)
#define CH   (LQ / SPLIT)   // 1764 keys per chunk
#define DP2  (DP / 2)       // 14 packed f32x2 values
#define SKIP_THR 18.0f      // log2 skip; measured dropped mass ~1e-9 at 22

typedef unsigned long long u64;

// Scratch (no allocations allowed -> device globals)
__device__ __align__(16) float g_K[LQ * DP];          // x patches (keys/vals)
__device__ __align__(16) float g_Q[LQ * DP];          // y patches (queries)
__device__ float g_yyc[LQ];                            // ||X_m||^2 * log2e/0.35
__device__ float g_pm[SPLIT * LQ];                     // partial max (log2 dom)
__device__ __align__(16) float g_pacc[SPLIT * LQ * DP]; // [..27] holds ssum
__device__ __align__(16) float g_outP[LQ * DP];        // attention out patches

__device__ __forceinline__ float ex2(float x) {
    float r;
    asm("ex2.approx.ftz.f32 %0, %1;" : "=f"(r) : "f"(x));
    return r;
}
__device__ __forceinline__ u64 pack2(float a, float b) {
    u64 r;
    asm("mov.b64 %0, {%1, %2};" : "=l"(r) : "f"(a), "f"(b));
    return r;
}
__device__ __forceinline__ void unpack2(u64 v, float& a, float& b) {
    asm("mov.b64 {%0, %1}, %2;" : "=f"(a), "=f"(b) : "l"(v));
}
// d = a*b + c  (packed 2x fp32)
__device__ __forceinline__ u64 fma2v(u64 a, u64 b, u64 c) {
    u64 d;
    asm("fma.rn.f32x2 %0, %1, %2, %3;" : "=l"(d) : "l"(a), "l"(b), "l"(c));
    return d;
}
__device__ __forceinline__ u64 add2v(u64 a, u64 b) {
    u64 d;
    asm("add.rn.f32x2 %0, %1, %2;" : "=l"(d) : "l"(a), "l"(b));
    return d;
}
__device__ __forceinline__ u64 mul2v(u64 a, u64 b) {
    u64 d;
    asm("mul.rn.f32x2 %0, %1, %2;" : "=l"(d) : "l"(a), "l"(b));
    return d;
}
// load two adjacent u64 (16B) from shared
__device__ __forceinline__ void lds_v2u64(u64& a, u64& b, const void* p) {
    asm("ld.shared.v2.b64 {%0, %1}, [%2];"
        : "=l"(a), "=l"(b) : "l"((size_t)__cvta_generic_to_shared(p)));
}

// ---------------------------------------------------------------------------
// Kernel A: patch extraction + key squared norms. K pad=1.0, Q pad=0.0
// ---------------------------------------------------------------------------
__global__ void extract_kernel(const float* __restrict__ x,
                               const float* __restrict__ y) {
    int m = blockIdx.x * blockDim.x + threadIdx.x;
    if (m >= LQ) return;
    int ph = m / HO, pw = m % HO;
    const float YSC = 1.4426950408889634f / 0.35f;   // log2e / (h^2 + 0.1)
    float yy = 0.f;
#pragma unroll
    for (int c = 0; c < 3; c++)
#pragma unroll
        for (int ki = 0; ki < 3; ki++)
#pragma unroll
            for (int kj = 0; kj < 3; kj++) {
                int j = c * 9 + ki * 3 + kj;
                float vx = x[c * 16384 + (ph + ki) * 128 + (pw + kj)];
                float vy = y[c * 16384 + (ph + ki) * 128 + (pw + kj)];
                g_K[m * DP + j] = vx;
                g_Q[m * DP + j] = vy;
                yy = fmaf(vx, vx, yy);
            }
    g_K[m * DP + 27] = 1.0f;     // ssum-in-accumulator trick
    g_Q[m * DP + 27] = 0.0f;     // keeps dot product exact
    g_yyc[m] = yy * YSC;
}

// ---------------------------------------------------------------------------
// Kernel B: flash attention, split-K, packed f32x2 math, threshold skip.
// 2D lane mapping (4x8 query block per warp -> correlated skip sets).
// Inner key loop unrolled x2 so two keys' LDS+dot chains interleave.
// score (log2 domain): sc = dot * (2*log2e/0.35) - yyc[m]
// acc[27] accumulates the softmax mass (K pad element = 1).
// ---------------------------------------------------------------------------
__global__ __launch_bounds__(BQ, 2) void attn_kernel() {
    __shared__ __align__(16) float sK[BK * DP];
    __shared__ float sY[BK];

    int tid = threadIdx.x;
    int w = tid >> 5;                       // warp 0..7
    int lane = tid & 31;
    // CTA tile: 16x16 queries at (bh*16, bw*16); warp subtile 4x8
    int bh = blockIdx.x >> 3, bw = blockIdx.x & 7;
    int qrow = min(bh * 16 + (w >> 1) * 4 + (lane >> 3), HO - 1);
    int qcol = min(bw * 16 + (w & 1) * 8 + (lane & 7), HO - 1);
    int ql = qrow * HO + qcol;

    int k0 = blockIdx.y * CH;

    const float S2 = 2.0f * 1.4426950408889634f / 0.35f;

    u64 qv[DP2];
#pragma unroll
    for (int p = 0; p < DP2 / 2; p++) {
        ulonglong2 t = ((const ulonglong2*)&g_Q[ql * DP])[p];
        qv[2 * p] = t.x; qv[2 * p + 1] = t.y;
    }
    u64 acc[DP2];
#pragma unroll
    for (int j = 0; j < DP2; j++) acc[j] = 0ull;
    float mmax = -CUDART_INF_F;

#pragma unroll 1
    for (int tile = 0; tile < CH / BK; tile++) {
        int kt = k0 + tile * BK;
        for (int t = tid; t < BK * (DP / 4); t += BQ) {
            ((float4*)sK)[t] = ((const float4*)g_K)[kt * (DP / 4) + t];
        }
        for (int t = tid; t < BK; t += BQ) sY[t] = g_yyc[kt + t];
        __syncthreads();

#pragma unroll 2
        for (int kk = 0; kk < BK; kk++) {
            const char* krow = (const char*)&sK[kk * DP];
            u64 kv[DP2];
#pragma unroll
            for (int p = 0; p < DP2 / 2; p++)
                lds_v2u64(kv[2 * p], kv[2 * p + 1], krow + 16 * p);

            // packed dot product, 2 chains
            u64 d0 = fma2v(qv[0], kv[0], 0ull);
            u64 d1 = fma2v(qv[1], kv[1], 0ull);
#pragma unroll
            for (int j = 2; j < DP2; j += 2) {
                d0 = fma2v(qv[j], kv[j], d0);
                d1 = fma2v(qv[j + 1], kv[j + 1], d1);
            }
            d0 = add2v(d0, d1);
            float lo, hi;
            unpack2(d0, lo, hi);
            float sc = fmaf(lo + hi, S2, -sY[kk]);

            // warp-uniform skip: negligible keys never touch ex2 / acc
            if (__any_sync(0xffffffffu, sc > mmax - SKIP_THR)) {
                if (sc > mmax) {            // rare rescale (peaked softmax)
                    float corr = ex2(mmax - sc);
                    u64 c2 = pack2(corr, corr);
#pragma unroll
                    for (int j = 0; j < DP2; j++) acc[j] = mul2v(acc[j], c2);
                    mmax = sc;
                }
                float p = ex2(sc - mmax);
                u64 p2 = pack2(p, p);
#pragma unroll
                for (int j = 0; j < DP2; j++)
                    acc[j] = fma2v(p2, kv[j], acc[j]);
            }
        }
        __syncthreads();
    }

    {
        int sidx = blockIdx.y * LQ + ql;
        g_pm[sidx] = mmax;
        ulonglong2* dst = (ulonglong2*)&g_pacc[(size_t)sidx * DP];
#pragma unroll
        for (int p = 0; p < DP2 / 2; p++) {
            ulonglong2 t;
            t.x = acc[2 * p]; t.y = acc[2 * p + 1];
            dst[p] = t;
        }
    }
}

// ---------------------------------------------------------------------------
// Kernel C: log-sum-exp merge of the SPLIT partials, normalize.
// o[27] = total softmax mass (from the K-pad trick)
// ---------------------------------------------------------------------------
__global__ void merge_kernel() {
    int q = blockIdx.x * blockDim.x + threadIdx.x;
    if (q >= LQ) return;
    float M = -CUDART_INF_F;
#pragma unroll
    for (int s = 0; s < SPLIT; s++) M = fmaxf(M, g_pm[s * LQ + q]);
    float o[DP];
#pragma unroll
    for (int j = 0; j < DP; j++) o[j] = 0.f;
#pragma unroll
    for (int s = 0; s < SPLIT; s++) {
        float w = ex2(g_pm[s * LQ + q] - M);
        const float4* src = (const float4*)&g_pacc[(size_t)(s * LQ + q) * DP];
#pragma unroll
        for (int p = 0; p < DP / 4; p++) {
            float4 t = src[p];
            o[4 * p]     = fmaf(t.x, w, o[4 * p]);
            o[4 * p + 1] = fmaf(t.y, w, o[4 * p + 1]);
            o[4 * p + 2] = fmaf(t.z, w, o[4 * p + 2]);
            o[4 * p + 3] = fmaf(t.w, w, o[4 * p + 3]);
        }
    }
    float inv = 1.0f / o[27];
#pragma unroll
    for (int p = 0; p < DP / 4; p++) {
        float4 t;
        t.x = o[4 * p] * inv; t.y = o[4 * p + 1] * inv;
        t.z = o[4 * p + 2] * inv; t.w = o[4 * p + 3] * inv;
        ((float4*)&g_outP[q * DP])[p] = t;
    }
}

// ---------------------------------------------------------------------------
// Kernel D: overlap-add fold with analytic contribution counts
// ---------------------------------------------------------------------------
__global__ void fold_kernel(float* __restrict__ out) {
    int idx = blockIdx.x * blockDim.x + threadIdx.x;
    if (idx >= 3 * 128 * 128) return;
    int c = idx / 16384;
    int h = (idx / 128) % 128;
    int w = idx % 128;
    int nh = min(h, 125) - max(0, h - 2) + 1;
    int nw = min(w, 125) - max(0, w - 2) + 1;
    float sum = 0.f;
#pragma unroll
    for (int ki = 0; ki < 3; ki++) {
        int ph = h - ki;
        if (ph < 0 || ph >= HO) continue;
#pragma unroll
        for (int kj = 0; kj < 3; kj++) {
            int pw = w - kj;
            if (pw < 0 || pw >= HO) continue;
            sum += g_outP[(ph * HO + pw) * DP + c * 9 + ki * 3 + kj];
        }
    }
    out[idx] = sum / (float)(nh * nw);
}

// ---------------------------------------------------------------------------
extern "C" void kernel_launch(void* const* d_in, const int* in_sizes, int n_in,
                              void* d_out, int out_size) {
    const float* x = (const float*)d_in[0];
    const float* y = (const float*)d_in[1];
    float* out = (float*)d_out;

    extract_kernel<<<(LQ + 255) / 256, 256>>>(x, y);
    dim3 grid(NQB, SPLIT);
    attn_kernel<<<grid, BQ>>>();
    merge_kernel<<<(LQ + 255) / 256, 256>>>();
    fold_kernel<<<(3 * 128 * 128 + 255) / 256, 256>>>(out);
}